// round 2
// baseline (speedup 1.0000x reference)
#include <cuda_runtime.h>
#include <cuda_bf16.h>
#include <math.h>

#define N_TOK 4096
#define HDIM  1024
#define FDIM  2816
#define NEXP  8
#define NA    (N_TOK * 2)      // assignments (top-2)
#define TM    128
#define TN    64
#define KB    32
#define PAD   36               // smem row stride (words), 16B-aligned, conflict-free
#define MAXMT 72               // max total m-tiles: 8192/128 + 8

// ---------------- scratch (static device allocations only) ----------------
__device__ float g_scores[NA];
__device__ int   g_eids[NA];
__device__ int   g_cnt[NEXP];
__device__ int   g_fill[NEXP];
__device__ int   g_off[NEXP + 1];
__device__ int   g_tileoff[NEXP + 1];
__device__ int   g_rows[NA];     // sorted pos -> token
__device__ int   g_aid[NA];      // sorted pos -> assignment id
__device__ __align__(16) float g_G[(size_t)NA * FDIM];  // GLU output (sorted-pos major)
__device__ __align__(16) float g_Y[(size_t)NA * HDIM];  // scaled expert outputs (aid major)

// ---------------- helpers ----------------
__device__ __forceinline__ unsigned f2tf(float x) {
    unsigned u;
    asm("cvt.rna.tf32.f32 %0, %1;" : "=r"(u) : "f"(x));
    return u;
}

__device__ __forceinline__ void mma8(float (&d)[4], const unsigned (&a)[4], const unsigned (&b)[2]) {
    asm volatile(
        "mma.sync.aligned.m16n8k8.row.col.f32.tf32.tf32.f32 "
        "{%0,%1,%2,%3},{%4,%5,%6,%7},{%8,%9},{%0,%1,%2,%3};\n"
        : "+f"(d[0]), "+f"(d[1]), "+f"(d[2]), "+f"(d[3])
        : "r"(a[0]), "r"(a[1]), "r"(a[2]), "r"(a[3]), "r"(b[0]), "r"(b[1]));
}

// ---------------- kernel 0: zero counters ----------------
__global__ void init_kernel() {
    if (threadIdx.x < NEXP) { g_cnt[threadIdx.x] = 0; g_fill[threadIdx.x] = 0; }
}

// ---------------- kernel 1: router (one block per token) ----------------
__global__ __launch_bounds__(256) void router_kernel(const float* __restrict__ x,
                                                     const float* __restrict__ wqkv) {
    __shared__ float sx[HDIM];
    __shared__ float sqkv[3 * NEXP];
    const int t = blockIdx.x;
    const float* xr = x + (size_t)t * HDIM;
    for (int i = threadIdx.x; i < HDIM; i += blockDim.x) sx[i] = xr[i];
    __syncthreads();

    const int w = threadIdx.x >> 5, lane = threadIdx.x & 31;
    // warp w computes rows w (q), w+8 (k), w+16 (v) of wqkv
    #pragma unroll
    for (int r = 0; r < 3; r++) {
        const int j = w + r * NEXP;
        const float* wr = wqkv + (size_t)j * HDIM;
        float s = 0.f;
        for (int i = lane; i < HDIM; i += 32) s += sx[i] * wr[i];
        #pragma unroll
        for (int o = 16; o; o >>= 1) s += __shfl_xor_sync(0xffffffffu, s, o);
        if (lane == 0) sqkv[j] = s;
    }
    __syncthreads();

    if (threadIdx.x == 0) {
        float q[NEXP], k[NEXP], v[NEXP], logit[NEXP];
        #pragma unroll
        for (int e = 0; e < NEXP; e++) { q[e] = sqkv[e]; k[e] = sqkv[e + 8]; v[e] = sqkv[e + 16]; }
        #pragma unroll
        for (int e = 0; e < NEXP; e++) {
            float a[NEXP], m = -1e30f;
            #pragma unroll
            for (int j = 0; j < NEXP; j++) { a[j] = q[e] * k[j]; m = fmaxf(m, a[j]); }
            float den = 0.f, num = 0.f;
            #pragma unroll
            for (int j = 0; j < NEXP; j++) { float ee = expf(a[j] - m); den += ee; num += ee * v[j]; }
            logit[e] = num / den;
        }
        // top-2 with jax tie-breaking (earliest index wins on ties)
        int i0 = 0;
        #pragma unroll
        for (int e = 1; e < NEXP; e++) if (logit[e] > logit[i0]) i0 = e;
        int i1 = (i0 == 0) ? 1 : 0;
        #pragma unroll
        for (int e = 0; e < NEXP; e++) if (e != i1 && e != i0 && logit[e] > logit[i1]) i1 = e;
        const float e1 = expf(logit[i1] - logit[i0]);
        const float inv = 1.f / (1.f + e1);
        g_scores[2 * t]     = inv;
        g_scores[2 * t + 1] = e1 * inv;
        g_eids[2 * t]     = i0;
        g_eids[2 * t + 1] = i1;
        atomicAdd(&g_cnt[i0], 1);
        atomicAdd(&g_cnt[i1], 1);
    }
}

// ---------------- kernel 2: exclusive scan over 8 experts ----------------
__global__ void scan_kernel() {
    if (threadIdx.x == 0 && blockIdx.x == 0) {
        int o = 0, tt = 0;
        for (int e = 0; e < NEXP; e++) {
            g_off[e] = o; g_tileoff[e] = tt;
            o += g_cnt[e];
            tt += (g_cnt[e] + TM - 1) / TM;
        }
        g_off[NEXP] = o; g_tileoff[NEXP] = tt;
    }
}

// ---------------- kernel 3: scatter assignments into expert buckets ----------------
__global__ void scatter_kernel() {
    const int a = blockIdx.x * blockDim.x + threadIdx.x;
    if (a < NA) {
        const int e = g_eids[a];
        const int p = g_off[e] + atomicAdd(&g_fill[e], 1);
        g_aid[p]  = a;
        g_rows[p] = a >> 1;
    }
}

// ---------------- kernel 4: grouped GEMM1 + fused GLU ----------------
// G[m, n] = silu(X[m]·w1[e][n]) * (X[m]·w1[e][F+n]),  m over sorted assignments of expert e
__global__ __launch_bounds__(256, 1) void gemm1_kernel(const float* __restrict__ x,
                                                       const float* __restrict__ w1) {
    const int mt = blockIdx.y;
    if (mt >= g_tileoff[NEXP]) return;
    int e = 0;
    #pragma unroll
    for (int i = 1; i < NEXP; i++) if (g_tileoff[i] <= mt) e = i;

    const int pbase = g_off[e];
    const int cnt   = g_off[e + 1] - pbase;
    const int m0    = (mt - g_tileoff[e]) * TM;
    const int n0    = blockIdx.x * TN;

    __shared__ unsigned As[TM][PAD];
    __shared__ unsigned Ba[TN][PAD];
    __shared__ unsigned Bg[TN][PAD];

    const int tid = threadIdx.x;
    const int lane = tid & 31, wp = tid >> 5;
    const int wm = wp & 3, wn = wp >> 2;
    const int g = lane >> 2, tg = lane & 3;

    // staging maps
    const int arow = tid >> 1;
    const int acol = (tid & 1) << 4;          // 0 or 16
    int am = m0 + arow; if (am >= cnt) am = cnt - 1;
    const float* aptr  = x + (size_t)g_rows[pbase + am] * HDIM + acol;
    const int brow = tid >> 2;
    const int bcol = (tid & 3) << 3;          // 0,8,16,24
    const float* baptr = w1 + ((size_t)e * 2 * FDIM + n0 + brow) * HDIM + bcol;
    const float* bgptr = baptr + (size_t)FDIM * HDIM;

    float accA[2][4][4] = {}, accG[2][4][4] = {};
    float4 ra[4], rb[2], rg[2];

    #pragma unroll
    for (int i = 0; i < 4; i++) ra[i] = *(const float4*)(aptr + 4 * i);
    #pragma unroll
    for (int i = 0; i < 2; i++) rb[i] = *(const float4*)(baptr + 4 * i);
    #pragma unroll
    for (int i = 0; i < 2; i++) rg[i] = *(const float4*)(bgptr + 4 * i);

    const int NC = HDIM / KB;
    #pragma unroll 1
    for (int c = 0; c < NC; c++) {
        __syncthreads();
        #pragma unroll
        for (int i = 0; i < 4; i++) {
            As[arow][acol + 4 * i + 0] = f2tf(ra[i].x);
            As[arow][acol + 4 * i + 1] = f2tf(ra[i].y);
            As[arow][acol + 4 * i + 2] = f2tf(ra[i].z);
            As[arow][acol + 4 * i + 3] = f2tf(ra[i].w);
        }
        #pragma unroll
        for (int i = 0; i < 2; i++) {
            Ba[brow][bcol + 4 * i + 0] = f2tf(rb[i].x);
            Ba[brow][bcol + 4 * i + 1] = f2tf(rb[i].y);
            Ba[brow][bcol + 4 * i + 2] = f2tf(rb[i].z);
            Ba[brow][bcol + 4 * i + 3] = f2tf(rb[i].w);
            Bg[brow][bcol + 4 * i + 0] = f2tf(rg[i].x);
            Bg[brow][bcol + 4 * i + 1] = f2tf(rg[i].y);
            Bg[brow][bcol + 4 * i + 2] = f2tf(rg[i].z);
            Bg[brow][bcol + 4 * i + 3] = f2tf(rg[i].w);
        }
        __syncthreads();
        if (c + 1 < NC) {
            const int k0 = (c + 1) * KB;
            #pragma unroll
            for (int i = 0; i < 4; i++) ra[i] = *(const float4*)(aptr + k0 + 4 * i);
            #pragma unroll
            for (int i = 0; i < 2; i++) rb[i] = *(const float4*)(baptr + k0 + 4 * i);
            #pragma unroll
            for (int i = 0; i < 2; i++) rg[i] = *(const float4*)(bgptr + k0 + 4 * i);
        }
        #pragma unroll
        for (int k8 = 0; k8 < KB / 8; k8++) {
            unsigned af[2][4], bfa[4][2], bfg[4][2];
            const int kk = k8 * 8 + tg;
            #pragma unroll
            for (int mi = 0; mi < 2; mi++) {
                const int r = wm * 32 + mi * 16 + g;
                af[mi][0] = As[r][kk];     af[mi][1] = As[r + 8][kk];
                af[mi][2] = As[r][kk + 4]; af[mi][3] = As[r + 8][kk + 4];
            }
            #pragma unroll
            for (int ni = 0; ni < 4; ni++) {
                const int nn = wn * 32 + ni * 8 + g;
                bfa[ni][0] = Ba[nn][kk]; bfa[ni][1] = Ba[nn][kk + 4];
                bfg[ni][0] = Bg[nn][kk]; bfg[ni][1] = Bg[nn][kk + 4];
            }
            #pragma unroll
            for (int mi = 0; mi < 2; mi++)
                #pragma unroll
                for (int ni = 0; ni < 4; ni++) {
                    mma8(accA[mi][ni], af[mi], bfa[ni]);
                    mma8(accG[mi][ni], af[mi], bfg[ni]);
                }
        }
    }

    // epilogue: GLU
    #pragma unroll
    for (int mi = 0; mi < 2; mi++)
        #pragma unroll
        for (int ni = 0; ni < 4; ni++)
            #pragma unroll
            for (int r = 0; r < 4; r++) {
                const int row = wm * 32 + mi * 16 + g + (r >> 1) * 8;
                const int col = wn * 32 + ni * 8 + tg * 2 + (r & 1);
                const int m = m0 + row;
                if (m < cnt) {
                    const float a = accA[mi][ni][r];
                    const float s = a / (1.f + expf(-a));
                    g_G[(size_t)(pbase + m) * FDIM + n0 + col] = s * accG[mi][ni][r];
                }
            }
}

// ---------------- kernel 5: grouped GEMM2 (+score scale) ----------------
// Y[aid, n] = score[aid] * (G[m]·w2[e][n])
__global__ __launch_bounds__(256, 1) void gemm2_kernel(const float* __restrict__ w2) {
    const int mt = blockIdx.y;
    if (mt >= g_tileoff[NEXP]) return;
    int e = 0;
    #pragma unroll
    for (int i = 1; i < NEXP; i++) if (g_tileoff[i] <= mt) e = i;

    const int pbase = g_off[e];
    const int cnt   = g_off[e + 1] - pbase;
    const int m0    = (mt - g_tileoff[e]) * TM;
    const int n0    = blockIdx.x * TN;

    __shared__ unsigned As[TM][PAD];
    __shared__ unsigned Bs[TN][PAD];

    const int tid = threadIdx.x;
    const int lane = tid & 31, wp = tid >> 5;
    const int wm = wp & 3, wn = wp >> 2;
    const int g = lane >> 2, tg = lane & 3;

    const int arow = tid >> 1;
    const int acol = (tid & 1) << 4;
    int am = m0 + arow; if (am >= cnt) am = cnt - 1;
    const float* aptr = g_G + (size_t)(pbase + am) * FDIM + acol;
    const int brow = tid >> 2;
    const int bcol = (tid & 3) << 3;
    const float* bptr = w2 + ((size_t)e * HDIM + n0 + brow) * FDIM + bcol;

    float acc[2][4][4] = {};
    float4 ra[4], rb[2];
    #pragma unroll
    for (int i = 0; i < 4; i++) ra[i] = *(const float4*)(aptr + 4 * i);
    #pragma unroll
    for (int i = 0; i < 2; i++) rb[i] = *(const float4*)(bptr + 4 * i);

    const int NC = FDIM / KB;  // 88
    #pragma unroll 1
    for (int c = 0; c < NC; c++) {
        __syncthreads();
        #pragma unroll
        for (int i = 0; i < 4; i++) {
            As[arow][acol + 4 * i + 0] = f2tf(ra[i].x);
            As[arow][acol + 4 * i + 1] = f2tf(ra[i].y);
            As[arow][acol + 4 * i + 2] = f2tf(ra[i].z);
            As[arow][acol + 4 * i + 3] = f2tf(ra[i].w);
        }
        #pragma unroll
        for (int i = 0; i < 2; i++) {
            Bs[brow][bcol + 4 * i + 0] = f2tf(rb[i].x);
            Bs[brow][bcol + 4 * i + 1] = f2tf(rb[i].y);
            Bs[brow][bcol + 4 * i + 2] = f2tf(rb[i].z);
            Bs[brow][bcol + 4 * i + 3] = f2tf(rb[i].w);
        }
        __syncthreads();
        if (c + 1 < NC) {
            const int k0 = (c + 1) * KB;
            #pragma unroll
            for (int i = 0; i < 4; i++) ra[i] = *(const float4*)(aptr + k0 + 4 * i);
            #pragma unroll
            for (int i = 0; i < 2; i++) rb[i] = *(const float4*)(bptr + k0 + 4 * i);
        }
        #pragma unroll
        for (int k8 = 0; k8 < KB / 8; k8++) {
            unsigned af[2][4], bf[4][2];
            const int kk = k8 * 8 + tg;
            #pragma unroll
            for (int mi = 0; mi < 2; mi++) {
                const int r = wm * 32 + mi * 16 + g;
                af[mi][0] = As[r][kk];     af[mi][1] = As[r + 8][kk];
                af[mi][2] = As[r][kk + 4]; af[mi][3] = As[r + 8][kk + 4];
            }
            #pragma unroll
            for (int ni = 0; ni < 4; ni++) {
                const int nn = wn * 32 + ni * 8 + g;
                bf[ni][0] = Bs[nn][kk]; bf[ni][1] = Bs[nn][kk + 4];
            }
            #pragma unroll
            for (int mi = 0; mi < 2; mi++)
                #pragma unroll
                for (int ni = 0; ni < 4; ni++) mma8(acc[mi][ni], af[mi], bf[ni]);
        }
    }

    // epilogue: scale by routing score, scatter into per-assignment Y
    #pragma unroll
    for (int mi = 0; mi < 2; mi++)
        #pragma unroll
        for (int h = 0; h < 2; h++) {
            const int row = wm * 32 + mi * 16 + g + h * 8;
            const int m = m0 + row;
            if (m < cnt) {
                const int aid = g_aid[pbase + m];
                const float s = g_scores[aid];
                float* yrow = g_Y + (size_t)aid * HDIM + n0;
                #pragma unroll
                for (int ni = 0; ni < 4; ni++) {
                    const int col = wn * 32 + ni * 8 + tg * 2;
                    yrow[col]     = s * acc[mi][ni][h * 2];
                    yrow[col + 1] = s * acc[mi][ni][h * 2 + 1];
                }
            }
        }
}

// ---------------- kernel 6: top-2 combine ----------------
__global__ void combine_kernel(float* __restrict__ out) {
    const int i = blockIdx.x * blockDim.x + threadIdx.x;
    if (i >= N_TOK * HDIM / 4) return;
    const int t = i >> 8;            // HDIM/4 = 256
    const int c = i & 255;
    const float4* y = (const float4*)g_Y;
    const float4 a = y[(size_t)(2 * t) * 256 + c];
    const float4 b = y[(size_t)(2 * t + 1) * 256 + c];
    float4 r;
    r.x = a.x + b.x; r.y = a.y + b.y; r.z = a.z + b.z; r.w = a.w + b.w;
    ((float4*)out)[i] = r;
}

// ---------------- launch ----------------
extern "C" void kernel_launch(void* const* d_in, const int* in_sizes, int n_in,
                              void* d_out, int out_size) {
    const float* x    = (const float*)d_in[0];  // (2,2048,1024)
    const float* wqkv = (const float*)d_in[1];  // (24,1024)
    const float* w1   = (const float*)d_in[2];  // (8,5632,1024)
    const float* w2   = (const float*)d_in[3];  // (8,1024,2816)
    float* out = (float*)d_out;

    init_kernel<<<1, 32>>>();
    router_kernel<<<N_TOK, 256>>>(x, wqkv);
    scan_kernel<<<1, 32>>>();
    scatter_kernel<<<(NA + 255) / 256, 256>>>();
    gemm1_kernel<<<dim3(FDIM / TN, MAXMT), 256>>>(x, w1);
    gemm2_kernel<<<dim3(HDIM / TN, MAXMT), 256>>>(w2);
    combine_kernel<<<(N_TOK * HDIM / 4 + 255) / 256, 256>>>(out);
}

// round 5
// speedup vs baseline: 2.5457x; 2.5457x over previous
#include <cuda_runtime.h>
#include <cuda_fp16.h>
#include <math.h>
#include <stdint.h>

#define N_TOK 4096
#define HDIM  1024
#define FDIM  2816
#define NEXP  8
#define NA    (N_TOK * 2)      // assignments (top-2)
#define TM    128              // m-tile rows
#define KB    64               // k halves per chunk = 128 B per smem row
#define STAGE 32768            // A tile 16KB + B tile 16KB
#define NSTG  3
#define SMEM_DYN (NSTG * STAGE)
#define MAXMT 72               // max total m-tiles: 8192/128 + 7

// ---------------- scratch (static device allocations only) ----------------
__device__ float g_scores[NA];
__device__ int   g_eids[NA];
__device__ int   g_cnt[NEXP];
__device__ int   g_fill[NEXP];
__device__ int   g_off[NEXP + 1];
__device__ int   g_tileoff[NEXP + 1];
__device__ int   g_rows[NA];     // sorted pos -> token
__device__ int   g_aid[NA];      // sorted pos -> assignment id
__device__ __align__(16) __half g_xh[(size_t)N_TOK * HDIM];
__device__ __align__(16) __half g_w1h[(size_t)NEXP * 2 * FDIM * HDIM];
__device__ __align__(16) __half g_w2h[(size_t)NEXP * HDIM * FDIM];
__device__ __align__(16) __half g_Gh[(size_t)NA * FDIM];   // GLU output fp16

// ---------------- helpers ----------------
__device__ __forceinline__ uint32_t smem_u32(const void* p) {
    uint32_t a;
    asm("{ .reg .u64 t; cvta.to.shared.u64 t, %1; cvt.u32.u64 %0, t; }" : "=r"(a) : "l"(p));
    return a;
}
__device__ __forceinline__ uint32_t sw(uint32_t off) {   // SW128 swizzle: chunk ^= row&7
    return off ^ ((off >> 3) & 0x70);
}
#define CP16(dst, src) \
    asm volatile("cp.async.cg.shared.global [%0], [%1], 16;" :: "r"(dst), "l"(src))
#define CPCOMMIT() asm volatile("cp.async.commit_group;" ::: "memory")
#define CPWAIT1()  asm volatile("cp.async.wait_group 1;" ::: "memory")
#define LDM4(r0, r1, r2, r3, addr) \
    asm volatile("ldmatrix.sync.aligned.m8n8.x4.shared.b16 {%0,%1,%2,%3},[%4];" \
                 : "=r"(r0), "=r"(r1), "=r"(r2), "=r"(r3) : "r"(addr))
__device__ __forceinline__ void mma16(float* d, const uint32_t* a, uint32_t b0, uint32_t b1) {
    asm volatile(
        "mma.sync.aligned.m16n8k16.row.col.f32.f16.f16.f32 "
        "{%0,%1,%2,%3},{%4,%5,%6,%7},{%8,%9},{%0,%1,%2,%3};"
        : "+f"(d[0]), "+f"(d[1]), "+f"(d[2]), "+f"(d[3])
        : "r"(a[0]), "r"(a[1]), "r"(a[2]), "r"(a[3]), "r"(b0), "r"(b1));
}

// ---------------- kernel: fp32 -> fp16 weight convert ----------------
__global__ void convert_kernel(const float* __restrict__ w1, const float* __restrict__ w2) {
    const size_t U1 = (size_t)NEXP * 2 * FDIM * HDIM / 8;
    const size_t U2 = (size_t)NEXP * HDIM * FDIM / 8;
    const size_t i = (size_t)blockIdx.x * blockDim.x + threadIdx.x;
    const float* src;
    __half* dst;
    if (i < U1)           { src = w1 + i * 8;        dst = g_w1h + i * 8; }
    else if (i < U1 + U2) { src = w2 + (i - U1) * 8; dst = g_w2h + (i - U1) * 8; }
    else return;
    const float4 v0 = ((const float4*)src)[0];
    const float4 v1 = ((const float4*)src)[1];
    __half2 h0 = __floats2half2_rn(v0.x, v0.y);
    __half2 h1 = __floats2half2_rn(v0.z, v0.w);
    __half2 h2 = __floats2half2_rn(v1.x, v1.y);
    __half2 h3 = __floats2half2_rn(v1.z, v1.w);
    uint4 o;
    o.x = *(uint32_t*)&h0; o.y = *(uint32_t*)&h1;
    o.z = *(uint32_t*)&h2; o.w = *(uint32_t*)&h3;
    *(uint4*)dst = o;
}

// ---------------- kernel: zero output ----------------
__global__ void zero_kernel(float* __restrict__ out) {
    const int i = blockIdx.x * blockDim.x + threadIdx.x;
    if (i < N_TOK * HDIM / 4) ((float4*)out)[i] = make_float4(0.f, 0.f, 0.f, 0.f);
}

// ---------------- kernel: init counters ----------------
__global__ void init_kernel() {
    if (threadIdx.x < NEXP) { g_cnt[threadIdx.x] = 0; g_fill[threadIdx.x] = 0; }
}

// ---------------- kernel: router (+ x fp16 convert) ----------------
__global__ __launch_bounds__(256) void router_kernel(const float* __restrict__ x,
                                                     const float* __restrict__ wqkv) {
    __shared__ float sx[HDIM];
    __shared__ float sqkv[3 * NEXP];
    const int t = blockIdx.x;
    const float* xr = x + (size_t)t * HDIM;
    for (int i = threadIdx.x; i < HDIM; i += blockDim.x) sx[i] = xr[i];
    __syncthreads();

    // write fp16 copy of this token row
    for (int i = threadIdx.x; i < HDIM; i += blockDim.x)
        g_xh[(size_t)t * HDIM + i] = __float2half(sx[i]);

    const int w = threadIdx.x >> 5, lane = threadIdx.x & 31;
    #pragma unroll
    for (int r = 0; r < 3; r++) {
        const int j = w + r * NEXP;
        const float* wr = wqkv + (size_t)j * HDIM;
        float s = 0.f;
        for (int i = lane; i < HDIM; i += 32) s += sx[i] * wr[i];
        #pragma unroll
        for (int o = 16; o; o >>= 1) s += __shfl_xor_sync(0xffffffffu, s, o);
        if (lane == 0) sqkv[j] = s;
    }
    __syncthreads();

    if (threadIdx.x == 0) {
        float q[NEXP], k[NEXP], v[NEXP], logit[NEXP];
        #pragma unroll
        for (int e = 0; e < NEXP; e++) { q[e] = sqkv[e]; k[e] = sqkv[e + 8]; v[e] = sqkv[e + 16]; }
        #pragma unroll
        for (int e = 0; e < NEXP; e++) {
            float a[NEXP], m = -1e30f;
            #pragma unroll
            for (int j = 0; j < NEXP; j++) { a[j] = q[e] * k[j]; m = fmaxf(m, a[j]); }
            float den = 0.f, num = 0.f;
            #pragma unroll
            for (int j = 0; j < NEXP; j++) { float ee = expf(a[j] - m); den += ee; num += ee * v[j]; }
            logit[e] = num / den;
        }
        int i0 = 0;
        #pragma unroll
        for (int e = 1; e < NEXP; e++) if (logit[e] > logit[i0]) i0 = e;
        int i1 = (i0 == 0) ? 1 : 0;
        #pragma unroll
        for (int e = 0; e < NEXP; e++) if (e != i1 && e != i0 && logit[e] > logit[i1]) i1 = e;
        const float e1 = expf(logit[i1] - logit[i0]);
        const float inv = 1.f / (1.f + e1);
        g_scores[2 * t]     = inv;
        g_scores[2 * t + 1] = e1 * inv;
        g_eids[2 * t]     = i0;
        g_eids[2 * t + 1] = i1;
        atomicAdd(&g_cnt[i0], 1);
        atomicAdd(&g_cnt[i1], 1);
    }
}

// ---------------- kernel: scan ----------------
__global__ void scan_kernel() {
    if (threadIdx.x == 0 && blockIdx.x == 0) {
        int o = 0, tt = 0;
        for (int e = 0; e < NEXP; e++) {
            g_off[e] = o; g_tileoff[e] = tt;
            o += g_cnt[e];
            tt += (g_cnt[e] + TM - 1) / TM;
        }
        g_off[NEXP] = o; g_tileoff[NEXP] = tt;
    }
}

// ---------------- kernel: scatter ----------------
__global__ void scatter_kernel() {
    const int a = blockIdx.x * blockDim.x + threadIdx.x;
    if (a < NA) {
        const int e = g_eids[a];
        const int p = g_off[e] + atomicAdd(&g_fill[e], 1);
        g_aid[p]  = a;
        g_rows[p] = a >> 1;
    }
}

// ---------------- kernel: grouped GEMM1 (fp16 HMMA) + fused GLU ----------------
// Block: 128 m-rows x 64 GLU cols. B smem rows interleave a/g so each acc
// (even,odd) col pair is (a,g) of one GLU column -> thread-local GLU epilogue.
__global__ __launch_bounds__(256, 2) void gemm1_kernel() {
    const int mt = blockIdx.x;
    if (mt >= g_tileoff[NEXP]) return;
    int e = 0;
    #pragma unroll
    for (int i = 1; i < NEXP; i++) if (g_tileoff[i] <= mt) e = i;
    const int pbase = g_off[e];
    const int cnt   = g_off[e + 1] - pbase;
    const int m0    = (mt - g_tileoff[e]) * TM;
    const int nb    = blockIdx.y * 64;            // GLU col base

    extern __shared__ __align__(1024) char smem[];
    const uint32_t sb = smem_u32(smem);
    const int tid = threadIdx.x, wid = tid >> 5, lane = tid & 31;
    const int wm = wid & 3, wn = wid >> 2;
    const int sel = lane >> 3, li = lane & 7;
    const int g = lane >> 2, tg = lane & 3;

    // cp.async staging: thread -> (row = tid/2, 64B half = tid&1)
    const int r = tid >> 1, hh = tid & 1;
    int am = m0 + r; if (am >= cnt) am = cnt - 1;
    const char* asrc = (const char*)(g_xh + (size_t)g_rows[pbase + am] * HDIM) + hh * 64;
    const int wrow = e * 2 * FDIM + ((r & 1) ? FDIM : 0) + nb + (r >> 1);  // a/g interleave
    const char* bsrc = (const char*)(g_w1h + (size_t)wrow * HDIM) + hh * 64;
    uint32_t adst[4], bdst[4];
    #pragma unroll
    for (int i = 0; i < 4; i++) {
        const uint32_t off = r * 128 + hh * 64 + i * 16;
        adst[i] = sw(off);
        bdst[i] = 16384 + sw(off);
    }

    // ldmatrix per-thread base offsets
    uint32_t aoff[2], boff[4];
    #pragma unroll
    for (int mi = 0; mi < 2; mi++)
        aoff[mi] = (uint32_t)(wm * 32 + mi * 16 + (sel & 1) * 8 + li) * 128 + (sel >> 1) * 16;
    #pragma unroll
    for (int p = 0; p < 4; p++)
        boff[p] = 16384 + (uint32_t)(wn * 64 + p * 16 + (sel >> 1) * 8 + li) * 128 + (sel & 1) * 16;

    float acc[2][8][4];
    #pragma unroll
    for (int mi = 0; mi < 2; mi++)
        #pragma unroll
        for (int ni = 0; ni < 8; ni++)
            #pragma unroll
            for (int q = 0; q < 4; q++) acc[mi][ni][q] = 0.f;

    auto stage = [&](int c, int s) {
        const uint32_t base = sb + s * STAGE;
        const char* ga = asrc + (size_t)c * 128;
        const char* gb = bsrc + (size_t)c * 128;
        #pragma unroll
        for (int i = 0; i < 4; i++) CP16(base + adst[i], ga + i * 16);
        #pragma unroll
        for (int i = 0; i < 4; i++) CP16(base + bdst[i], gb + i * 16);
        CPCOMMIT();
    };

    const int NC = HDIM / KB;  // 16
    stage(0, 0); stage(1, 1);
    for (int c = 0; c < NC; c++) {
        const int s = c % NSTG;
        CPWAIT1();
        __syncthreads();
        if (c + 2 < NC) stage(c + 2, (c + 2) % NSTG);
        const uint32_t sbase = sb + s * STAGE;
        #pragma unroll
        for (int j = 0; j < 4; j++) {
            uint32_t a[2][4];
            #pragma unroll
            for (int mi = 0; mi < 2; mi++)
                LDM4(a[mi][0], a[mi][1], a[mi][2], a[mi][3], sbase + sw(aoff[mi] + j * 32));
            #pragma unroll
            for (int p = 0; p < 4; p++) {
                uint32_t b0, b1, b2, b3;
                LDM4(b0, b1, b2, b3, sbase + sw(boff[p] + j * 32));
                #pragma unroll
                for (int mi = 0; mi < 2; mi++) {
                    mma16(acc[mi][2 * p],     a[mi], b0, b1);
                    mma16(acc[mi][2 * p + 1], a[mi], b2, b3);
                }
            }
        }
    }

    // GLU epilogue: d even col = a, odd col = g of GLU col (n/2)
    #pragma unroll
    for (int mi = 0; mi < 2; mi++)
        #pragma unroll
        for (int h = 0; h < 2; h++) {
            const int m = m0 + wm * 32 + mi * 16 + g + h * 8;
            if (m < cnt) {
                __half* gp = g_Gh + (size_t)(pbase + m) * FDIM + nb + wn * 32;
                #pragma unroll
                for (int ni = 0; ni < 8; ni++) {
                    const float a  = acc[mi][ni][h * 2];
                    const float gg = acc[mi][ni][h * 2 + 1];
                    gp[ni * 4 + tg] = __float2half(a / (1.f + expf(-a)) * gg);
                }
            }
        }
}

// ---------------- kernel: grouped GEMM2 (fp16 HMMA) + score scale + atomic combine --------
__global__ __launch_bounds__(256, 2) void gemm2_kernel(float* __restrict__ out) {
    const int mt = blockIdx.x;
    if (mt >= g_tileoff[NEXP]) return;
    int e = 0;
    #pragma unroll
    for (int i = 1; i < NEXP; i++) if (g_tileoff[i] <= mt) e = i;
    const int pbase = g_off[e];
    const int cnt   = g_off[e + 1] - pbase;
    const int m0    = (mt - g_tileoff[e]) * TM;
    const int nb    = blockIdx.y * 128;           // output col base

    extern __shared__ __align__(1024) char smem[];
    const uint32_t sb = smem_u32(smem);
    const int tid = threadIdx.x, wid = tid >> 5, lane = tid & 31;
    const int wm = wid & 3, wn = wid >> 2;
    const int sel = lane >> 3, li = lane & 7;
    const int g = lane >> 2, tg = lane & 3;

    const int r = tid >> 1, hh = tid & 1;
    int am = m0 + r; if (am >= cnt) am = cnt - 1;
    const char* asrc = (const char*)(g_Gh + (size_t)(pbase + am) * FDIM) + hh * 64;
    const char* bsrc = (const char*)(g_w2h + ((size_t)e * HDIM + nb + r) * FDIM) + hh * 64;
    uint32_t adst[4], bdst[4];
    #pragma unroll
    for (int i = 0; i < 4; i++) {
        const uint32_t off = r * 128 + hh * 64 + i * 16;
        adst[i] = sw(off);
        bdst[i] = 16384 + sw(off);
    }

    uint32_t aoff[2], boff[4];
    #pragma unroll
    for (int mi = 0; mi < 2; mi++)
        aoff[mi] = (uint32_t)(wm * 32 + mi * 16 + (sel & 1) * 8 + li) * 128 + (sel >> 1) * 16;
    #pragma unroll
    for (int p = 0; p < 4; p++)
        boff[p] = 16384 + (uint32_t)(wn * 64 + p * 16 + (sel >> 1) * 8 + li) * 128 + (sel & 1) * 16;

    float acc[2][8][4];
    #pragma unroll
    for (int mi = 0; mi < 2; mi++)
        #pragma unroll
        for (int ni = 0; ni < 8; ni++)
            #pragma unroll
            for (int q = 0; q < 4; q++) acc[mi][ni][q] = 0.f;

    auto stage = [&](int c, int s) {
        const uint32_t base = sb + s * STAGE;
        const char* ga = asrc + (size_t)c * 128;
        const char* gb = bsrc + (size_t)c * 128;
        #pragma unroll
        for (int i = 0; i < 4; i++) CP16(base + adst[i], ga + i * 16);
        #pragma unroll
        for (int i = 0; i < 4; i++) CP16(base + bdst[i], gb + i * 16);
        CPCOMMIT();
    };

    const int NC = FDIM / KB;  // 44
    stage(0, 0); stage(1, 1);
    for (int c = 0; c < NC; c++) {
        const int s = c % NSTG;
        CPWAIT1();
        __syncthreads();
        if (c + 2 < NC) stage(c + 2, (c + 2) % NSTG);
        const uint32_t sbase = sb + s * STAGE;
        #pragma unroll
        for (int j = 0; j < 4; j++) {
            uint32_t a[2][4];
            #pragma unroll
            for (int mi = 0; mi < 2; mi++)
                LDM4(a[mi][0], a[mi][1], a[mi][2], a[mi][3], sbase + sw(aoff[mi] + j * 32));
            #pragma unroll
            for (int p = 0; p < 4; p++) {
                uint32_t b0, b1, b2, b3;
                LDM4(b0, b1, b2, b3, sbase + sw(boff[p] + j * 32));
                #pragma unroll
                for (int mi = 0; mi < 2; mi++) {
                    mma16(acc[mi][2 * p],     a[mi], b0, b1);
                    mma16(acc[mi][2 * p + 1], a[mi], b2, b3);
                }
            }
        }
    }

    // epilogue: scale by routing score, atomic top-2 combine into out
    // (exactly 2 commutative fp32 adds per output cell -> deterministic)
    #pragma unroll
    for (int mi = 0; mi < 2; mi++)
        #pragma unroll
        for (int h = 0; h < 2; h++) {
            const int m = m0 + wm * 32 + mi * 16 + g + h * 8;
            if (m < cnt) {
                const int aid  = g_aid[pbase + m];
                const float sc = g_scores[aid];
                float* op = out + (size_t)(aid >> 1) * HDIM + nb + wn * 64;
                #pragma unroll
                for (int ni = 0; ni < 8; ni++) {
                    const int c0 = ni * 8 + 2 * tg;
                    atomicAdd(op + c0,     sc * acc[mi][ni][h * 2]);
                    atomicAdd(op + c0 + 1, sc * acc[mi][ni][h * 2 + 1]);
                }
            }
        }
}

// ---------------- launch ----------------
extern "C" void kernel_launch(void* const* d_in, const int* in_sizes, int n_in,
                              void* d_out, int out_size) {
    const float* x    = (const float*)d_in[0];  // (2,2048,1024)
    const float* wqkv = (const float*)d_in[1];  // (24,1024)
    const float* w1   = (const float*)d_in[2];  // (8,5632,1024)
    const float* w2   = (const float*)d_in[3];  // (8,1024,2816)
    float* out = (float*)d_out;

    cudaFuncSetAttribute(gemm1_kernel, cudaFuncAttributeMaxDynamicSharedMemorySize, SMEM_DYN);
    cudaFuncSetAttribute(gemm2_kernel, cudaFuncAttributeMaxDynamicSharedMemorySize, SMEM_DYN);

    const int conv_units = (NEXP * 2 * FDIM * HDIM + NEXP * HDIM * FDIM) / 8;
    convert_kernel<<<(conv_units + 255) / 256, 256>>>(w1, w2);
    zero_kernel<<<(N_TOK * HDIM / 4 + 255) / 256, 256>>>(out);
    init_kernel<<<1, 32>>>();
    router_kernel<<<N_TOK, 256>>>(x, wqkv);
    scan_kernel<<<1, 32>>>();
    scatter_kernel<<<(NA + 255) / 256, 256>>>();
    gemm1_kernel<<<dim3(MAXMT, FDIM / 64), 256, SMEM_DYN>>>();
    gemm2_kernel<<<dim3(MAXMT, HDIM / 128), 256, SMEM_DYN>>>(out);
}

// round 6
// speedup vs baseline: 2.5667x; 1.0082x over previous
#include <cuda_runtime.h>
#include <cuda_fp16.h>
#include <math.h>
#include <stdint.h>

#define N_TOK 4096
#define HDIM  1024
#define FDIM  2816
#define NEXP  8
#define NA    (N_TOK * 2)      // assignments (top-2)
#define TM    128              // m-tile rows
#define KB    64               // k halves per chunk = 128 B per smem row
#define STAGE 32768            // A tile 16KB + B tile 16KB
#define NSTG  3
#define SMEM_DYN (NSTG * STAGE)
#define MAXMT 72               // max total m-tiles: 8192/128 + 7

// ---------------- scratch (static device allocations only) ----------------
__device__ float g_scores[NA];
__device__ int   g_eids[NA];
__device__ int   g_cnt[NEXP];
__device__ int   g_fill[NEXP];
__device__ int   g_off[NEXP + 1];
__device__ int   g_tileoff[NEXP + 1];
__device__ int   g_rows[NA];     // sorted pos -> token
__device__ int   g_aid[NA];      // sorted pos -> assignment id
__device__ __align__(16) __half g_xh[(size_t)N_TOK * HDIM];
__device__ __align__(16) __half g_w1h[(size_t)NEXP * 2 * FDIM * HDIM];
__device__ __align__(16) __half g_w2h[(size_t)NEXP * HDIM * FDIM];
__device__ __align__(16) __half g_Gh[(size_t)NA * FDIM];   // GLU output fp16

// ---------------- helpers ----------------
__device__ __forceinline__ uint32_t smem_u32(const void* p) {
    uint32_t a;
    asm("{ .reg .u64 t; cvta.to.shared.u64 t, %1; cvt.u32.u64 %0, t; }" : "=r"(a) : "l"(p));
    return a;
}
__device__ __forceinline__ uint32_t sw(uint32_t off) {   // SW128 swizzle: chunk ^= row&7
    return off ^ ((off >> 3) & 0x70);
}
#define CP16(dst, src) \
    asm volatile("cp.async.cg.shared.global [%0], [%1], 16;" :: "r"(dst), "l"(src))
#define CPCOMMIT() asm volatile("cp.async.commit_group;" ::: "memory")
#define CPWAIT1()  asm volatile("cp.async.wait_group 1;" ::: "memory")
#define LDM4(r0, r1, r2, r3, addr) \
    asm volatile("ldmatrix.sync.aligned.m8n8.x4.shared.b16 {%0,%1,%2,%3},[%4];" \
                 : "=r"(r0), "=r"(r1), "=r"(r2), "=r"(r3) : "r"(addr))
__device__ __forceinline__ void mma16(float* d, const uint32_t* a, uint32_t b0, uint32_t b1) {
    asm volatile(
        "mma.sync.aligned.m16n8k16.row.col.f32.f16.f16.f32 "
        "{%0,%1,%2,%3},{%4,%5,%6,%7},{%8,%9},{%0,%1,%2,%3};"
        : "+f"(d[0]), "+f"(d[1]), "+f"(d[2]), "+f"(d[3])
        : "r"(a[0]), "r"(a[1]), "r"(a[2]), "r"(a[3]), "r"(b0), "r"(b1));
}

// ---------------- launch 0: fp32 -> fp16 weight convert (+ counter init) ------
__global__ void convert_kernel(const float* __restrict__ w1, const float* __restrict__ w2) {
    if (blockIdx.x == 0 && threadIdx.x < NEXP) {
        g_cnt[threadIdx.x] = 0; g_fill[threadIdx.x] = 0;
    }
    const size_t U1 = (size_t)NEXP * 2 * FDIM * HDIM / 8;
    const size_t U2 = (size_t)NEXP * HDIM * FDIM / 8;
    const size_t i = (size_t)blockIdx.x * blockDim.x + threadIdx.x;
    const float* src;
    __half* dst;
    if (i < U1)           { src = w1 + i * 8;        dst = g_w1h + i * 8; }
    else if (i < U1 + U2) { src = w2 + (i - U1) * 8; dst = g_w2h + (i - U1) * 8; }
    else return;
    const float4 v0 = ((const float4*)src)[0];
    const float4 v1 = ((const float4*)src)[1];
    __half2 h0 = __floats2half2_rn(v0.x, v0.y);
    __half2 h1 = __floats2half2_rn(v0.z, v0.w);
    __half2 h2 = __floats2half2_rn(v1.x, v1.y);
    __half2 h3 = __floats2half2_rn(v1.z, v1.w);
    uint4 o;
    o.x = *(uint32_t*)&h0; o.y = *(uint32_t*)&h1;
    o.z = *(uint32_t*)&h2; o.w = *(uint32_t*)&h3;
    *(uint4*)dst = o;
}

// ---------------- launch 1: router (+ x fp16 convert) ----------------
__global__ __launch_bounds__(256) void router_kernel(const float* __restrict__ x,
                                                     const float* __restrict__ wqkv) {
    __shared__ float sx[HDIM];
    __shared__ float sqkv[3 * NEXP];
    const int t = blockIdx.x;
    const float* xr = x + (size_t)t * HDIM;
    for (int i = threadIdx.x; i < HDIM; i += blockDim.x) sx[i] = xr[i];
    __syncthreads();

    // write fp16 copy of this token row
    for (int i = threadIdx.x; i < HDIM; i += blockDim.x)
        g_xh[(size_t)t * HDIM + i] = __float2half(sx[i]);

    const int w = threadIdx.x >> 5, lane = threadIdx.x & 31;
    #pragma unroll
    for (int r = 0; r < 3; r++) {
        const int j = w + r * NEXP;
        const float* wr = wqkv + (size_t)j * HDIM;
        float s = 0.f;
        for (int i = lane; i < HDIM; i += 32) s += sx[i] * wr[i];
        #pragma unroll
        for (int o = 16; o; o >>= 1) s += __shfl_xor_sync(0xffffffffu, s, o);
        if (lane == 0) sqkv[j] = s;
    }
    __syncthreads();

    // warp 0: lanes 0..7 each compute logit[e] in parallel (same per-e math as serial version)
    if (w == 0) {
        float logit = -1e30f;
        if (lane < NEXP) {
            const float qe = sqkv[lane];
            float a[NEXP], m = -1e30f;
            #pragma unroll
            for (int j = 0; j < NEXP; j++) { a[j] = qe * sqkv[8 + j]; m = fmaxf(m, a[j]); }
            float den = 0.f, num = 0.f;
            #pragma unroll
            for (int j = 0; j < NEXP; j++) {
                float ee = expf(a[j] - m);
                den += ee; num += ee * sqkv[16 + j];
            }
            logit = num / den;
        }
        // gather the 8 logits to lane 0 via shuffle
        float lg[NEXP];
        #pragma unroll
        for (int e = 0; e < NEXP; e++) lg[e] = __shfl_sync(0xffffffffu, logit, e);
        if (lane == 0) {
            int i0 = 0;
            #pragma unroll
            for (int e = 1; e < NEXP; e++) if (lg[e] > lg[i0]) i0 = e;
            int i1 = (i0 == 0) ? 1 : 0;
            #pragma unroll
            for (int e = 0; e < NEXP; e++) if (e != i1 && e != i0 && lg[e] > lg[i1]) i1 = e;
            const float e1 = expf(lg[i1] - lg[i0]);
            const float inv = 1.f / (1.f + e1);
            g_scores[2 * t]     = inv;
            g_scores[2 * t + 1] = e1 * inv;
            g_eids[2 * t]     = i0;
            g_eids[2 * t + 1] = i1;
            atomicAdd(&g_cnt[i0], 1);
            atomicAdd(&g_cnt[i1], 1);
        }
    }
}

// ---------------- launch 2: scatter (each block re-derives the 8-expert scan) --
__global__ void scatter_kernel() {
    // every block computes the tiny scan in registers from g_cnt
    int off[NEXP + 1], tileoff[NEXP + 1];
    int o = 0, tt = 0;
    #pragma unroll
    for (int e = 0; e < NEXP; e++) {
        off[e] = o; tileoff[e] = tt;
        o += g_cnt[e];
        tt += (g_cnt[e] + TM - 1) / TM;
    }
    off[NEXP] = o; tileoff[NEXP] = tt;

    if (blockIdx.x == 0 && threadIdx.x == 0) {
        #pragma unroll
        for (int e = 0; e <= NEXP; e++) { g_off[e] = off[e]; g_tileoff[e] = tileoff[e]; }
    }

    const int a = blockIdx.x * blockDim.x + threadIdx.x;
    if (a < NA) {
        const int e = g_eids[a];
        const int p = off[e] + atomicAdd(&g_fill[e], 1);
        g_aid[p]  = a;
        g_rows[p] = a >> 1;
    }
}

// ---------------- launch 3: grouped GEMM1 (fp16 HMMA) + fused GLU -------------
// Block: 128 m-rows x 64 GLU cols. B smem rows interleave a/g so each acc
// (even,odd) col pair is (a,g) of one GLU column -> thread-local GLU epilogue.
__global__ __launch_bounds__(256, 2) void gemm1_kernel() {
    const int mt = blockIdx.x;
    if (mt >= g_tileoff[NEXP]) return;
    int e = 0;
    #pragma unroll
    for (int i = 1; i < NEXP; i++) if (g_tileoff[i] <= mt) e = i;
    const int pbase = g_off[e];
    const int cnt   = g_off[e + 1] - pbase;
    const int m0    = (mt - g_tileoff[e]) * TM;
    const int nb    = blockIdx.y * 64;            // GLU col base

    extern __shared__ __align__(1024) char smem[];
    const uint32_t sb = smem_u32(smem);
    const int tid = threadIdx.x, wid = tid >> 5, lane = tid & 31;
    const int wm = wid & 3, wn = wid >> 2;
    const int sel = lane >> 3, li = lane & 7;
    const int g = lane >> 2, tg = lane & 3;

    // cp.async staging: thread -> (row = tid/2, 64B half = tid&1)
    const int r = tid >> 1, hh = tid & 1;
    int am = m0 + r; if (am >= cnt) am = cnt - 1;
    const char* asrc = (const char*)(g_xh + (size_t)g_rows[pbase + am] * HDIM) + hh * 64;
    const int wrow = e * 2 * FDIM + ((r & 1) ? FDIM : 0) + nb + (r >> 1);  // a/g interleave
    const char* bsrc = (const char*)(g_w1h + (size_t)wrow * HDIM) + hh * 64;
    uint32_t adst[4], bdst[4];
    #pragma unroll
    for (int i = 0; i < 4; i++) {
        const uint32_t off = r * 128 + hh * 64 + i * 16;
        adst[i] = sw(off);
        bdst[i] = 16384 + sw(off);
    }

    // ldmatrix per-thread base offsets
    uint32_t aoff[2], boff[4];
    #pragma unroll
    for (int mi = 0; mi < 2; mi++)
        aoff[mi] = (uint32_t)(wm * 32 + mi * 16 + (sel & 1) * 8 + li) * 128 + (sel >> 1) * 16;
    #pragma unroll
    for (int p = 0; p < 4; p++)
        boff[p] = 16384 + (uint32_t)(wn * 64 + p * 16 + (sel >> 1) * 8 + li) * 128 + (sel & 1) * 16;

    float acc[2][8][4];
    #pragma unroll
    for (int mi = 0; mi < 2; mi++)
        #pragma unroll
        for (int ni = 0; ni < 8; ni++)
            #pragma unroll
            for (int q = 0; q < 4; q++) acc[mi][ni][q] = 0.f;

    auto stage = [&](int c, int s) {
        const uint32_t base = sb + s * STAGE;
        const char* ga = asrc + (size_t)c * 128;
        const char* gb = bsrc + (size_t)c * 128;
        #pragma unroll
        for (int i = 0; i < 4; i++) CP16(base + adst[i], ga + i * 16);
        #pragma unroll
        for (int i = 0; i < 4; i++) CP16(base + bdst[i], gb + i * 16);
        CPCOMMIT();
    };

    const int NC = HDIM / KB;  // 16
    stage(0, 0); stage(1, 1);
    for (int c = 0; c < NC; c++) {
        const int s = c % NSTG;
        CPWAIT1();
        __syncthreads();
        if (c + 2 < NC) stage(c + 2, (c + 2) % NSTG);
        const uint32_t sbase = sb + s * STAGE;
        #pragma unroll
        for (int j = 0; j < 4; j++) {
            uint32_t a[2][4];
            #pragma unroll
            for (int mi = 0; mi < 2; mi++)
                LDM4(a[mi][0], a[mi][1], a[mi][2], a[mi][3], sbase + sw(aoff[mi] + j * 32));
            #pragma unroll
            for (int p = 0; p < 4; p++) {
                uint32_t b0, b1, b2, b3;
                LDM4(b0, b1, b2, b3, sbase + sw(boff[p] + j * 32));
                #pragma unroll
                for (int mi = 0; mi < 2; mi++) {
                    mma16(acc[mi][2 * p],     a[mi], b0, b1);
                    mma16(acc[mi][2 * p + 1], a[mi], b2, b3);
                }
            }
        }
    }

    // GLU epilogue: d even col = a, odd col = g of GLU col (n/2)
    #pragma unroll
    for (int mi = 0; mi < 2; mi++)
        #pragma unroll
        for (int h = 0; h < 2; h++) {
            const int m = m0 + wm * 32 + mi * 16 + g + h * 8;
            if (m < cnt) {
                __half* gp = g_Gh + (size_t)(pbase + m) * FDIM + nb + wn * 32;
                #pragma unroll
                for (int ni = 0; ni < 8; ni++) {
                    const float a  = acc[mi][ni][h * 2];
                    const float gg = acc[mi][ni][h * 2 + 1];
                    gp[ni * 4 + tg] = __float2half(a / (1.f + expf(-a)) * gg);
                }
            }
        }
}

// ---------------- launch 4: zero output ----------------
__global__ void zero_kernel(float* __restrict__ out) {
    const int i = blockIdx.x * blockDim.x + threadIdx.x;
    if (i < N_TOK * HDIM / 4) ((float4*)out)[i] = make_float4(0.f, 0.f, 0.f, 0.f);
}

// ---------------- launch 5: grouped GEMM2 (fp16 HMMA) + score + atomic combine
__global__ __launch_bounds__(256, 2) void gemm2_kernel(float* __restrict__ out) {
    const int mt = blockIdx.x;
    if (mt >= g_tileoff[NEXP]) return;
    int e = 0;
    #pragma unroll
    for (int i = 1; i < NEXP; i++) if (g_tileoff[i] <= mt) e = i;
    const int pbase = g_off[e];
    const int cnt   = g_off[e + 1] - pbase;
    const int m0    = (mt - g_tileoff[e]) * TM;
    const int nb    = blockIdx.y * 128;           // output col base

    extern __shared__ __align__(1024) char smem[];
    const uint32_t sb = smem_u32(smem);
    const int tid = threadIdx.x, wid = tid >> 5, lane = tid & 31;
    const int wm = wid & 3, wn = wid >> 2;
    const int sel = lane >> 3, li = lane & 7;
    const int g = lane >> 2, tg = lane & 3;

    const int r = tid >> 1, hh = tid & 1;
    int am = m0 + r; if (am >= cnt) am = cnt - 1;
    const char* asrc = (const char*)(g_Gh + (size_t)(pbase + am) * FDIM) + hh * 64;
    const char* bsrc = (const char*)(g_w2h + ((size_t)e * HDIM + nb + r) * FDIM) + hh * 64;
    uint32_t adst[4], bdst[4];
    #pragma unroll
    for (int i = 0; i < 4; i++) {
        const uint32_t off = r * 128 + hh * 64 + i * 16;
        adst[i] = sw(off);
        bdst[i] = 16384 + sw(off);
    }

    uint32_t aoff[2], boff[4];
    #pragma unroll
    for (int mi = 0; mi < 2; mi++)
        aoff[mi] = (uint32_t)(wm * 32 + mi * 16 + (sel & 1) * 8 + li) * 128 + (sel >> 1) * 16;
    #pragma unroll
    for (int p = 0; p < 4; p++)
        boff[p] = 16384 + (uint32_t)(wn * 64 + p * 16 + (sel >> 1) * 8 + li) * 128 + (sel & 1) * 16;

    float acc[2][8][4];
    #pragma unroll
    for (int mi = 0; mi < 2; mi++)
        #pragma unroll
        for (int ni = 0; ni < 8; ni++)
            #pragma unroll
            for (int q = 0; q < 4; q++) acc[mi][ni][q] = 0.f;

    auto stage = [&](int c, int s) {
        const uint32_t base = sb + s * STAGE;
        const char* ga = asrc + (size_t)c * 128;
        const char* gb = bsrc + (size_t)c * 128;
        #pragma unroll
        for (int i = 0; i < 4; i++) CP16(base + adst[i], ga + i * 16);
        #pragma unroll
        for (int i = 0; i < 4; i++) CP16(base + bdst[i], gb + i * 16);
        CPCOMMIT();
    };

    const int NC = FDIM / KB;  // 44
    stage(0, 0); stage(1, 1);
    for (int c = 0; c < NC; c++) {
        const int s = c % NSTG;
        CPWAIT1();
        __syncthreads();
        if (c + 2 < NC) stage(c + 2, (c + 2) % NSTG);
        const uint32_t sbase = sb + s * STAGE;
        #pragma unroll
        for (int j = 0; j < 4; j++) {
            uint32_t a[2][4];
            #pragma unroll
            for (int mi = 0; mi < 2; mi++)
                LDM4(a[mi][0], a[mi][1], a[mi][2], a[mi][3], sbase + sw(aoff[mi] + j * 32));
            #pragma unroll
            for (int p = 0; p < 4; p++) {
                uint32_t b0, b1, b2, b3;
                LDM4(b0, b1, b2, b3, sbase + sw(boff[p] + j * 32));
                #pragma unroll
                for (int mi = 0; mi < 2; mi++) {
                    mma16(acc[mi][2 * p],     a[mi], b0, b1);
                    mma16(acc[mi][2 * p + 1], a[mi], b2, b3);
                }
            }
        }
    }

    // epilogue: scale by routing score, atomic top-2 combine into out
    // (exactly 2 commutative fp32 adds per output cell -> deterministic)
    #pragma unroll
    for (int mi = 0; mi < 2; mi++)
        #pragma unroll
        for (int h = 0; h < 2; h++) {
            const int m = m0 + wm * 32 + mi * 16 + g + h * 8;
            if (m < cnt) {
                const int aid  = g_aid[pbase + m];
                const float sc = g_scores[aid];
                float* op = out + (size_t)(aid >> 1) * HDIM + nb + wn * 64;
                #pragma unroll
                for (int ni = 0; ni < 8; ni++) {
                    const int c0 = ni * 8 + 2 * tg;
                    atomicAdd(op + c0,     sc * acc[mi][ni][h * 2]);
                    atomicAdd(op + c0 + 1, sc * acc[mi][ni][h * 2 + 1]);
                }
            }
        }
}

// ---------------- launch ----------------
extern "C" void kernel_launch(void* const* d_in, const int* in_sizes, int n_in,
                              void* d_out, int out_size) {
    const float* x    = (const float*)d_in[0];  // (2,2048,1024)
    const float* wqkv = (const float*)d_in[1];  // (24,1024)
    const float* w1   = (const float*)d_in[2];  // (8,5632,1024)
    const float* w2   = (const float*)d_in[3];  // (8,1024,2816)
    float* out = (float*)d_out;

    cudaFuncSetAttribute(gemm1_kernel, cudaFuncAttributeMaxDynamicSharedMemorySize, SMEM_DYN);
    cudaFuncSetAttribute(gemm2_kernel, cudaFuncAttributeMaxDynamicSharedMemorySize, SMEM_DYN);

    const int conv_units = (NEXP * 2 * FDIM * HDIM + NEXP * HDIM * FDIM) / 8;
    convert_kernel<<<(conv_units + 255) / 256, 256>>>(w1, w2);            // 0
    router_kernel<<<N_TOK, 256>>>(x, wqkv);                               // 1
    scatter_kernel<<<(NA + 255) / 256, 256>>>();                          // 2
    gemm1_kernel<<<dim3(MAXMT, FDIM / 64), 256, SMEM_DYN>>>();            // 3  <- profiled
    zero_kernel<<<(N_TOK * HDIM / 4 + 255) / 256, 256>>>(out);            // 4
    gemm2_kernel<<<dim3(MAXMT, HDIM / 128), 256, SMEM_DYN>>>(out);        // 5
}

// round 8
// speedup vs baseline: 2.7157x; 1.0581x over previous
#include <cuda_runtime.h>
#include <cuda_fp16.h>
#include <math.h>
#include <stdint.h>

#define N_TOK 4096
#define HDIM  1024
#define FDIM  2816
#define NEXP  8
#define NA    (N_TOK * 2)      // assignments (top-2)
#define TM    128              // m-tile rows
#define KB    64               // k halves per chunk = 128 B per smem row
#define STAGE 32768            // A tile 16KB + B tile 16KB
#define NSTG  3
#define SMEM_DYN (NSTG * STAGE)
#define MAXMT 72               // max total m-tiles: 8192/128 + 7

// ---------------- scratch (static device allocations only) ----------------
__device__ float g_scores[NA];
__device__ int   g_eids[NA];
__device__ int   g_cnt[NEXP];
__device__ int   g_fill[NEXP];
__device__ int   g_off[NEXP + 1];
__device__ int   g_tileoff[NEXP + 1];
__device__ int   g_rows[NA];     // sorted pos -> token
__device__ int   g_aid[NA];      // sorted pos -> assignment id
__device__ __align__(16) __half g_xh[(size_t)N_TOK * HDIM];
__device__ __align__(16) __half g_w1h[(size_t)NEXP * 2 * FDIM * HDIM];
__device__ __align__(16) __half g_w2h[(size_t)NEXP * HDIM * FDIM];
__device__ __align__(16) __half g_Gh[(size_t)NA * FDIM];   // GLU output fp16

// ---------------- helpers ----------------
__device__ __forceinline__ uint32_t smem_u32(const void* p) {
    uint32_t a;
    asm("{ .reg .u64 t; cvta.to.shared.u64 t, %1; cvt.u32.u64 %0, t; }" : "=r"(a) : "l"(p));
    return a;
}
__device__ __forceinline__ uint32_t sw(uint32_t off) {   // SW128 swizzle: chunk ^= row&7
    return off ^ ((off >> 3) & 0x70);
}
#define CP16(dst, src) \
    asm volatile("cp.async.cg.shared.global [%0], [%1], 16;" :: "r"(dst), "l"(src))
#define CPCOMMIT() asm volatile("cp.async.commit_group;" ::: "memory")
#define CPWAIT1()  asm volatile("cp.async.wait_group 1;" ::: "memory")
#define CPWAIT0()  asm volatile("cp.async.wait_group 0;" ::: "memory")
#define LDM4(r0, r1, r2, r3, addr) \
    asm volatile("ldmatrix.sync.aligned.m8n8.x4.shared.b16 {%0,%1,%2,%3},[%4];" \
                 : "=r"(r0), "=r"(r1), "=r"(r2), "=r"(r3) : "r"(addr))
__device__ __forceinline__ void mma16(float* d, const uint32_t* a, uint32_t b0, uint32_t b1) {
    asm volatile(
        "mma.sync.aligned.m16n8k16.row.col.f32.f16.f16.f32 "
        "{%0,%1,%2,%3},{%4,%5,%6,%7},{%8,%9},{%0,%1,%2,%3};"
        : "+f"(d[0]), "+f"(d[1]), "+f"(d[2]), "+f"(d[3])
        : "r"(a[0]), "r"(a[1]), "r"(a[2]), "r"(a[3]), "r"(b0), "r"(b1));
}
// fragment loads (A: 2 x ldmatrix.x4 by mi; B: 1 x ldmatrix.x4 per p)
#define LDAF(dst, sbase, j) do { \
    LDM4((dst)[0][0], (dst)[0][1], (dst)[0][2], (dst)[0][3], (sbase) + sw(aoff[0] + (j) * 32)); \
    LDM4((dst)[1][0], (dst)[1][1], (dst)[1][2], (dst)[1][3], (sbase) + sw(aoff[1] + (j) * 32)); \
} while (0)
#define LDBF(dst, sbase, j, p) \
    LDM4((dst)[0], (dst)[1], (dst)[2], (dst)[3], (sbase) + sw(boff[p] + (j) * 32))

// ---------------- launch 0: fp32 -> fp16 weight convert (+ counter init) ------
__global__ void convert_kernel(const float* __restrict__ w1, const float* __restrict__ w2) {
    if (blockIdx.x == 0 && threadIdx.x < NEXP) {
        g_cnt[threadIdx.x] = 0; g_fill[threadIdx.x] = 0;
    }
    const size_t U1 = (size_t)NEXP * 2 * FDIM * HDIM / 8;
    const size_t U2 = (size_t)NEXP * HDIM * FDIM / 8;
    const size_t i = (size_t)blockIdx.x * blockDim.x + threadIdx.x;
    const float* src;
    __half* dst;
    if (i < U1)           { src = w1 + i * 8;        dst = g_w1h + i * 8; }
    else if (i < U1 + U2) { src = w2 + (i - U1) * 8; dst = g_w2h + (i - U1) * 8; }
    else return;
    const float4 v0 = ((const float4*)src)[0];
    const float4 v1 = ((const float4*)src)[1];
    __half2 h0 = __floats2half2_rn(v0.x, v0.y);
    __half2 h1 = __floats2half2_rn(v0.z, v0.w);
    __half2 h2 = __floats2half2_rn(v1.x, v1.y);
    __half2 h3 = __floats2half2_rn(v1.z, v1.w);
    uint4 o;
    o.x = *(uint32_t*)&h0; o.y = *(uint32_t*)&h1;
    o.z = *(uint32_t*)&h2; o.w = *(uint32_t*)&h3;
    *(uint4*)dst = o;
}

// ---------------- launch 1: router (+ x fp16 convert) ----------------
__global__ __launch_bounds__(256) void router_kernel(const float* __restrict__ x,
                                                     const float* __restrict__ wqkv) {
    __shared__ float sx[HDIM];
    __shared__ float sqkv[3 * NEXP];
    const int t = blockIdx.x;
    const float* xr = x + (size_t)t * HDIM;
    for (int i = threadIdx.x; i < HDIM; i += blockDim.x) sx[i] = xr[i];
    __syncthreads();

    for (int i = threadIdx.x; i < HDIM; i += blockDim.x)
        g_xh[(size_t)t * HDIM + i] = __float2half(sx[i]);

    const int w = threadIdx.x >> 5, lane = threadIdx.x & 31;
    #pragma unroll
    for (int r = 0; r < 3; r++) {
        const int j = w + r * NEXP;
        const float* wr = wqkv + (size_t)j * HDIM;
        float s = 0.f;
        for (int i = lane; i < HDIM; i += 32) s += sx[i] * wr[i];
        #pragma unroll
        for (int o = 16; o; o >>= 1) s += __shfl_xor_sync(0xffffffffu, s, o);
        if (lane == 0) sqkv[j] = s;
    }
    __syncthreads();

    if (w == 0) {
        float logit = -1e30f;
        if (lane < NEXP) {
            const float qe = sqkv[lane];
            float a[NEXP], m = -1e30f;
            #pragma unroll
            for (int j = 0; j < NEXP; j++) { a[j] = qe * sqkv[8 + j]; m = fmaxf(m, a[j]); }
            float den = 0.f, num = 0.f;
            #pragma unroll
            for (int j = 0; j < NEXP; j++) {
                float ee = expf(a[j] - m);
                den += ee; num += ee * sqkv[16 + j];
            }
            logit = num / den;
        }
        float lg[NEXP];
        #pragma unroll
        for (int e = 0; e < NEXP; e++) lg[e] = __shfl_sync(0xffffffffu, logit, e);
        if (lane == 0) {
            int i0 = 0;
            #pragma unroll
            for (int e = 1; e < NEXP; e++) if (lg[e] > lg[i0]) i0 = e;
            int i1 = (i0 == 0) ? 1 : 0;
            #pragma unroll
            for (int e = 0; e < NEXP; e++) if (e != i1 && e != i0 && lg[e] > lg[i1]) i1 = e;
            const float e1 = expf(lg[i1] - lg[i0]);
            const float inv = 1.f / (1.f + e1);
            g_scores[2 * t]     = inv;
            g_scores[2 * t + 1] = e1 * inv;
            g_eids[2 * t]     = i0;
            g_eids[2 * t + 1] = i1;
            atomicAdd(&g_cnt[i0], 1);
            atomicAdd(&g_cnt[i1], 1);
        }
    }
}

// ---------------- launch 2: scatter (each block re-derives the 8-expert scan) --
__global__ void scatter_kernel() {
    int off[NEXP + 1], tileoff[NEXP + 1];
    int o = 0, tt = 0;
    #pragma unroll
    for (int e = 0; e < NEXP; e++) {
        off[e] = o; tileoff[e] = tt;
        o += g_cnt[e];
        tt += (g_cnt[e] + TM - 1) / TM;
    }
    off[NEXP] = o; tileoff[NEXP] = tt;

    if (blockIdx.x == 0 && threadIdx.x == 0) {
        #pragma unroll
        for (int e = 0; e <= NEXP; e++) { g_off[e] = off[e]; g_tileoff[e] = tileoff[e]; }
    }

    const int a = blockIdx.x * blockDim.x + threadIdx.x;
    if (a < NA) {
        const int e = g_eids[a];
        const int p = off[e] + atomicAdd(&g_fill[e], 1);
        g_aid[p]  = a;
        g_rows[p] = a >> 1;
    }
}

// ---------------- launch 3: grouped GEMM1 (fp16 HMMA) + fused GLU -------------
__global__ __launch_bounds__(256, 2) void gemm1_kernel() {
    const int mt = blockIdx.x;
    if (mt >= g_tileoff[NEXP]) return;
    int e = 0;
    #pragma unroll
    for (int i = 1; i < NEXP; i++) if (g_tileoff[i] <= mt) e = i;
    const int pbase = g_off[e];
    const int cnt   = g_off[e + 1] - pbase;
    const int m0    = (mt - g_tileoff[e]) * TM;
    const int nb    = blockIdx.y * 64;            // GLU col base

    extern __shared__ __align__(1024) char smem[];
    const uint32_t sb = smem_u32(smem);
    const int tid = threadIdx.x, wid = tid >> 5, lane = tid & 31;
    const int wm = wid & 3, wn = wid >> 2;
    const int sel = lane >> 3, li = lane & 7;
    const int g = lane >> 2, tg = lane & 3;

    const int r = tid >> 1, hh = tid & 1;
    int am = m0 + r; if (am >= cnt) am = cnt - 1;
    const char* asrc = (const char*)(g_xh + (size_t)g_rows[pbase + am] * HDIM) + hh * 64;
    const int wrow = e * 2 * FDIM + ((r & 1) ? FDIM : 0) + nb + (r >> 1);  // a/g interleave
    const char* bsrc = (const char*)(g_w1h + (size_t)wrow * HDIM) + hh * 64;
    uint32_t adst[4], bdst[4];
    #pragma unroll
    for (int i = 0; i < 4; i++) {
        const uint32_t off = r * 128 + hh * 64 + i * 16;
        adst[i] = sw(off);
        bdst[i] = 16384 + sw(off);
    }

    uint32_t aoff[2], boff[4];
    #pragma unroll
    for (int mi = 0; mi < 2; mi++)
        aoff[mi] = (uint32_t)(wm * 32 + mi * 16 + (sel & 1) * 8 + li) * 128 + (sel >> 1) * 16;
    #pragma unroll
    for (int p = 0; p < 4; p++)
        boff[p] = 16384 + (uint32_t)(wn * 64 + p * 16 + (sel >> 1) * 8 + li) * 128 + (sel & 1) * 16;

    float acc[2][8][4];
    #pragma unroll
    for (int mi = 0; mi < 2; mi++)
        #pragma unroll
        for (int ni = 0; ni < 8; ni++)
            #pragma unroll
            for (int q = 0; q < 4; q++) acc[mi][ni][q] = 0.f;

    auto stage = [&](int c, int s) {
        const uint32_t base = sb + s * STAGE;
        const char* ga = asrc + (size_t)c * 128;
        const char* gb = bsrc + (size_t)c * 128;
        #pragma unroll
        for (int i = 0; i < 4; i++) CP16(base + adst[i], ga + i * 16);
        #pragma unroll
        for (int i = 0; i < 4; i++) CP16(base + bdst[i], gb + i * 16);
        CPCOMMIT();
    };

    // software-pipelined mainloop: parity ping-pong fragments
    uint32_t af[2][2][4], bf[2][4];
    const int NC = HDIM / KB;  // 16
    stage(0, 0); stage(1, 1);
    CPWAIT1();
    __syncthreads();
    LDAF(af[0], sb, 0);
    LDBF(bf[0], sb, 0, 0);

    for (int c = 0; c < NC; c++) {
        const uint32_t sbase = sb + (c % NSTG) * STAGE;
        #pragma unroll
        for (int j = 0; j < 4; j++) {
            #pragma unroll
            for (int p = 0; p < 4; p++) {
                if (p < 3) {
                    LDBF(bf[(p + 1) & 1], sbase, j, p + 1);
                } else if (j < 3) {
                    LDAF(af[(j + 1) & 1], sbase, j + 1);
                    LDBF(bf[0], sbase, j + 1, 0);
                }
                #pragma unroll
                for (int mi = 0; mi < 2; mi++) {
                    mma16(acc[mi][2 * p],     af[j & 1][mi], bf[p & 1][0], bf[p & 1][1]);
                    mma16(acc[mi][2 * p + 1], af[j & 1][mi], bf[p & 1][2], bf[p & 1][3]);
                }
            }
        }
        if (c + 1 < NC) {
            // RACE FIX: when no further stage is committed, wait for ALL groups
            // before prefetching from buffer (c+1)%3 (group c+1 must be complete).
            if (c + 2 < NC) { stage(c + 2, (c + 2) % NSTG); CPWAIT1(); }
            else           { CPWAIT0(); }
            __syncthreads();
            const uint32_t nbase = sb + ((c + 1) % NSTG) * STAGE;
            LDAF(af[0], nbase, 0);
            LDBF(bf[0], nbase, 0, 0);
        }
    }

    // GLU epilogue: d even col = a, odd col = g of GLU col (n/2)
    #pragma unroll
    for (int mi = 0; mi < 2; mi++)
        #pragma unroll
        for (int h = 0; h < 2; h++) {
            const int m = m0 + wm * 32 + mi * 16 + g + h * 8;
            if (m < cnt) {
                __half* gp = g_Gh + (size_t)(pbase + m) * FDIM + nb + wn * 32;
                #pragma unroll
                for (int ni = 0; ni < 8; ni++) {
                    const float a  = acc[mi][ni][h * 2];
                    const float gg = acc[mi][ni][h * 2 + 1];
                    gp[ni * 4 + tg] = __float2half(a / (1.f + expf(-a)) * gg);
                }
            }
        }
}

// ---------------- launch 4: zero output ----------------
__global__ void zero_kernel(float* __restrict__ out) {
    const int i = blockIdx.x * blockDim.x + threadIdx.x;
    if (i < N_TOK * HDIM / 4) ((float4*)out)[i] = make_float4(0.f, 0.f, 0.f, 0.f);
}

// ---------------- launch 5: grouped GEMM2 (fp16 HMMA) + score + atomic combine
__global__ __launch_bounds__(256, 2) void gemm2_kernel(float* __restrict__ out) {
    const int mt = blockIdx.x;
    if (mt >= g_tileoff[NEXP]) return;
    int e = 0;
    #pragma unroll
    for (int i = 1; i < NEXP; i++) if (g_tileoff[i] <= mt) e = i;
    const int pbase = g_off[e];
    const int cnt   = g_off[e + 1] - pbase;
    const int m0    = (mt - g_tileoff[e]) * TM;
    const int nb    = blockIdx.y * 128;           // output col base

    extern __shared__ __align__(1024) char smem[];
    const uint32_t sb = smem_u32(smem);
    const int tid = threadIdx.x, wid = tid >> 5, lane = tid & 31;
    const int wm = wid & 3, wn = wid >> 2;
    const int sel = lane >> 3, li = lane & 7;
    const int g = lane >> 2, tg = lane & 3;

    const int r = tid >> 1, hh = tid & 1;
    int am = m0 + r; if (am >= cnt) am = cnt - 1;
    const char* asrc = (const char*)(g_Gh + (size_t)(pbase + am) * FDIM) + hh * 64;
    const char* bsrc = (const char*)(g_w2h + ((size_t)e * HDIM + nb + r) * FDIM) + hh * 64;
    uint32_t adst[4], bdst[4];
    #pragma unroll
    for (int i = 0; i < 4; i++) {
        const uint32_t off = r * 128 + hh * 64 + i * 16;
        adst[i] = sw(off);
        bdst[i] = 16384 + sw(off);
    }

    uint32_t aoff[2], boff[4];
    #pragma unroll
    for (int mi = 0; mi < 2; mi++)
        aoff[mi] = (uint32_t)(wm * 32 + mi * 16 + (sel & 1) * 8 + li) * 128 + (sel >> 1) * 16;
    #pragma unroll
    for (int p = 0; p < 4; p++)
        boff[p] = 16384 + (uint32_t)(wn * 64 + p * 16 + (sel >> 1) * 8 + li) * 128 + (sel & 1) * 16;

    float acc[2][8][4];
    #pragma unroll
    for (int mi = 0; mi < 2; mi++)
        #pragma unroll
        for (int ni = 0; ni < 8; ni++)
            #pragma unroll
            for (int q = 0; q < 4; q++) acc[mi][ni][q] = 0.f;

    auto stage = [&](int c, int s) {
        const uint32_t base = sb + s * STAGE;
        const char* ga = asrc + (size_t)c * 128;
        const char* gb = bsrc + (size_t)c * 128;
        #pragma unroll
        for (int i = 0; i < 4; i++) CP16(base + adst[i], ga + i * 16);
        #pragma unroll
        for (int i = 0; i < 4; i++) CP16(base + bdst[i], gb + i * 16);
        CPCOMMIT();
    };

    uint32_t af[2][2][4], bf[2][4];
    const int NC = FDIM / KB;  // 44
    stage(0, 0); stage(1, 1);
    CPWAIT1();
    __syncthreads();
    LDAF(af[0], sb, 0);
    LDBF(bf[0], sb, 0, 0);

    for (int c = 0; c < NC; c++) {
        const uint32_t sbase = sb + (c % NSTG) * STAGE;
        #pragma unroll
        for (int j = 0; j < 4; j++) {
            #pragma unroll
            for (int p = 0; p < 4; p++) {
                if (p < 3) {
                    LDBF(bf[(p + 1) & 1], sbase, j, p + 1);
                } else if (j < 3) {
                    LDAF(af[(j + 1) & 1], sbase, j + 1);
                    LDBF(bf[0], sbase, j + 1, 0);
                }
                #pragma unroll
                for (int mi = 0; mi < 2; mi++) {
                    mma16(acc[mi][2 * p],     af[j & 1][mi], bf[p & 1][0], bf[p & 1][1]);
                    mma16(acc[mi][2 * p + 1], af[j & 1][mi], bf[p & 1][2], bf[p & 1][3]);
                }
            }
        }
        if (c + 1 < NC) {
            // RACE FIX: see gemm1 — drain all cp.async groups on the final tail.
            if (c + 2 < NC) { stage(c + 2, (c + 2) % NSTG); CPWAIT1(); }
            else           { CPWAIT0(); }
            __syncthreads();
            const uint32_t nbase = sb + ((c + 1) % NSTG) * STAGE;
            LDAF(af[0], nbase, 0);
            LDBF(bf[0], nbase, 0, 0);
        }
    }

    // epilogue: scale by routing score, atomic top-2 combine into out
    #pragma unroll
    for (int mi = 0; mi < 2; mi++)
        #pragma unroll
        for (int h = 0; h < 2; h++) {
            const int m = m0 + wm * 32 + mi * 16 + g + h * 8;
            if (m < cnt) {
                const int aid  = g_aid[pbase + m];
                const float sc = g_scores[aid];
                float* op = out + (size_t)(aid >> 1) * HDIM + nb + wn * 64;
                #pragma unroll
                for (int ni = 0; ni < 8; ni++) {
                    const int c0 = ni * 8 + 2 * tg;
                    atomicAdd(op + c0,     sc * acc[mi][ni][h * 2]);
                    atomicAdd(op + c0 + 1, sc * acc[mi][ni][h * 2 + 1]);
                }
            }
        }
}

// ---------------- launch ----------------
extern "C" void kernel_launch(void* const* d_in, const int* in_sizes, int n_in,
                              void* d_out, int out_size) {
    const float* x    = (const float*)d_in[0];  // (2,2048,1024)
    const float* wqkv = (const float*)d_in[1];  // (24,1024)
    const float* w1   = (const float*)d_in[2];  // (8,5632,1024)
    const float* w2   = (const float*)d_in[3];  // (8,1024,2816)
    float* out = (float*)d_out;

    cudaFuncSetAttribute(gemm1_kernel, cudaFuncAttributeMaxDynamicSharedMemorySize, SMEM_DYN);
    cudaFuncSetAttribute(gemm2_kernel, cudaFuncAttributeMaxDynamicSharedMemorySize, SMEM_DYN);

    const int conv_units = (NEXP * 2 * FDIM * HDIM + NEXP * HDIM * FDIM) / 8;
    convert_kernel<<<(conv_units + 255) / 256, 256>>>(w1, w2);            // 0
    router_kernel<<<N_TOK, 256>>>(x, wqkv);                               // 1
    scatter_kernel<<<(NA + 255) / 256, 256>>>();                          // 2
    gemm1_kernel<<<dim3(MAXMT, FDIM / 64), 256, SMEM_DYN>>>();            // 3  <- profiled
    zero_kernel<<<(N_TOK * HDIM / 4 + 255) / 256, 256>>>(out);            // 4
    gemm2_kernel<<<dim3(MAXMT, HDIM / 128), 256, SMEM_DYN>>>(out);        // 5
}